// round 16
// baseline (speedup 1.0000x reference)
#include <cuda_runtime.h>

// Salt & pepper noise apply: out = u < 0.01 ? 0 : (u < 0.02 ? 1 : x)
// Pure streaming elementwise, HBM-bound. 128-bit loads/stores, branch-free.

static __device__ __forceinline__ float sp(float x, float u) {
    // u < 0.01 -> 0 ; u < 0.02 -> 1 ; else x
    float v = (u < 0.02f) ? 1.0f : x;
    return (u < 0.01f) ? 0.0f : v;
}

__global__ void __launch_bounds__(256)
salt_pepper_kernel(const float4* __restrict__ img,
                   const float4* __restrict__ uni,
                   float4* __restrict__ out,
                   int n4) {
    int i = blockIdx.x * blockDim.x + threadIdx.x;
    if (i < n4) {
        float4 x = __ldg(&img[i]);
        float4 u = __ldg(&uni[i]);
        float4 r;
        r.x = sp(x.x, u.x);
        r.y = sp(x.y, u.y);
        r.z = sp(x.z, u.z);
        r.w = sp(x.w, u.w);
        out[i] = r;
    }
}

// Scalar tail fallback in case element count isn't divisible by 4
__global__ void salt_pepper_tail(const float* __restrict__ img,
                                 const float* __restrict__ uni,
                                 float* __restrict__ out,
                                 int start, int n) {
    int i = start + blockIdx.x * blockDim.x + threadIdx.x;
    if (i < n) {
        out[i] = sp(img[i], uni[i]);
    }
}

extern "C" void kernel_launch(void* const* d_in, const int* in_sizes, int n_in,
                              void* d_out, int out_size) {
    const float* img = (const float*)d_in[0];
    const float* uni = (const float*)d_in[1];
    float* out = (float*)d_out;
    int n = in_sizes[0];

    int n4 = n / 4;
    if (n4 > 0) {
        int threads = 256;
        int blocks = (n4 + threads - 1) / threads;
        salt_pepper_kernel<<<blocks, threads>>>(
            (const float4*)img, (const float4*)uni, (float4*)out, n4);
    }
    int rem = n - n4 * 4;
    if (rem > 0) {
        salt_pepper_tail<<<1, 256>>>(img, uni, out, n4 * 4, n);
    }
}